// round 11
// baseline (speedup 1.0000x reference)
#include <cuda_runtime.h>
#include <cuda_fp16.h>
#include <cstdint>

// HexConv, persistent-CTA fp16 mma.sync (m16n8k16, f32 accum), 24 warps,
// double-buffered fp16 grid, one barrier per batch:
//   warp grid = 4 N-quarters (16 cols) x 6 M-groups (frags f = 2*wm+u, u<2, f<11).
//   Per batch: convert(b+1) -> idle buffer issued before compute(b); single
//   end-of-iter __syncthreads publishes it and retires the old buffer.
// K-permutation: per 32-k superblock, thread lc owns orig d = 8lc..8lc+7 -> all
// operand loads are LDS.128; CELLB/WROWB == 64 mod 128 -> conflict-free phases.

#define NHEX   165
#define HD     64
#define OUTD   64
#define NCHUNK 7
#define CELLB  192
#define WROWB  960
#define NB     2048
#define THREADS 768
#define GRIDX  152

#define G_BYTES (221 * CELLB)                 // 42432 per buffer
#define W_BYTES (OUTD * WROWB)                // 61440
#define SMEM_BYTES (2 * G_BYTES + W_BYTES)    // 146304

__constant__ int OFFC[7] = {-17 * CELLB, -16 * CELLB, -1 * CELLB, 0,
                            1 * CELLB, 17 * CELLB, 18 * CELLB};

static __device__ __forceinline__ uint32_t pk(float a, float b) {
    __half2 h = __floats2half2_rn(a, b);
    return *(uint32_t*)&h;
}
static __device__ __forceinline__ void mma16816(float* c,
                                                uint32_t a0, uint32_t a1, uint32_t a2, uint32_t a3,
                                                uint32_t b0, uint32_t b1) {
    asm volatile(
        "mma.sync.aligned.m16n8k16.row.col.f32.f16.f16.f32 "
        "{%0,%1,%2,%3}, {%4,%5,%6,%7}, {%8,%9}, {%0,%1,%2,%3};"
        : "+f"(c[0]), "+f"(c[1]), "+f"(c[2]), "+f"(c[3])
        : "r"(a0), "r"(a1), "r"(a2), "r"(a3), "r"(b0), "r"(b1));
}

__global__ void __launch_bounds__(THREADS, 1)
hexconv_mma(const float* __restrict__ x, const float* __restrict__ W,
            const float* __restrict__ bias, float* __restrict__ out)
{
    extern __shared__ char smem[];
    char* G0 = smem;                       // grid buffer 0
    char* G1 = smem + G_BYTES;             // grid buffer 1
    char* Wc = smem + 2 * G_BYTES;         // W, fp16
    const int tid = threadIdx.x;

    // ---- one-time: zero both grid buffers (pad cells stay zero forever) ----
    for (int i = tid; i < 2 * G_BYTES / 16; i += THREADS)
        ((uint4*)smem)[i] = make_uint4(0, 0, 0, 0);

    // ---- one-time: stage W as fp16 ----
    const float4* Wg4 = (const float4*)W;
    for (int i = tid; i < OUTD * 112; i += THREADS) {
        int o = i / 112, k4 = i - o * 112;
        float4 v = Wg4[i];
        *(uint2*)(Wc + o * WROWB + k4 * 8) = make_uint2(pk(v.x, v.y), pk(v.z, v.w));
    }

    // ---- staging map: groups of 8 floats; thread owns g0=tid, g1=tid+768 ----
    const int g0 = tid, g1 = tid + THREADS;
    const bool v1 = (g1 < NHEX * 8);
    int dst0, dst1 = 0;
    {
        int n = g0 >> 3, d8 = g0 & 7;
        int hr = n / 15, hc = n - 15 * hr;
        dst0 = ((hr + 1) * 17 + (hc + 1)) * CELLB + d8 * 16;
        if (v1) {
            n = g1 >> 3; d8 = g1 & 7;
            hr = n / 15; hc = n - 15 * hr;
            dst1 = ((hr + 1) * 17 + (hc + 1)) * CELLB + d8 * 16;
        }
    }

    // ---- warp geometry: 24 warps = 4 N-quarters x 6 M-groups ----
    const int wid = tid >> 5, lane = tid & 31;
    const int wm = wid % 6;        // M group: frags f = 2*wm + u
    const int wn = wid / 6;        // N quarter (16 cols)
    const int lr = lane >> 2, lc = lane & 3;

    float2 bv[2];
#pragma unroll
    for (int nf = 0; nf < 2; nf++)
        bv[nf] = ((const float2*)bias)[(wn * 16 + nf * 8 + 2 * lc) >> 1];

    // fragment row bases (clamped): rows n = 16f + h*8 + lr
    int base2[2][2], parC[2][2];
#pragma unroll
    for (int u = 0; u < 2; u++) {
        const int f = 2 * wm + u;
#pragma unroll
        for (int h = 0; h < 2; h++) {
            int n = f * 16 + h * 8 + lr;
            if (n > 164) n = 164;
            int hr = n / 15, hc = n - 15 * hr;
            base2[u][h] = ((hr + 1) * 17 + (hc + 1)) * CELLB + 16 * lc;
            parC[u][h]  = ((hr + 1) & 1) ? CELLB : 0;
        }
    }

    __syncthreads();   // zero + W staging complete

    // ---- convert first batch into buffer 0 ----
    {
        const float4* xs = (const float4*)(x + (size_t)blockIdx.x * (NHEX * HD));
        float4 a0 = xs[2 * g0], a1 = xs[2 * g0 + 1];
        float4 c0, c1;
        if (v1) { c0 = xs[2 * g1]; c1 = xs[2 * g1 + 1]; }
        *(uint4*)(G0 + dst0) = make_uint4(pk(a0.x, a0.y), pk(a0.z, a0.w),
                                          pk(a1.x, a1.y), pk(a1.z, a1.w));
        if (v1)
            *(uint4*)(G0 + dst1) = make_uint4(pk(c0.x, c0.y), pk(c0.z, c0.w),
                                              pk(c1.x, c1.y), pk(c1.z, c1.w));
    }
    __syncthreads();   // buffer 0 ready

    int ib = 0;
    for (int b = blockIdx.x; b < NB; b += GRIDX) {
        char* cur = (ib == 0) ? G0 : G1;
        char* nxt = (ib == 0) ? G1 : G0;

        // ---- convert next batch into idle buffer (no barrier; overlaps compute) ----
        const int bn = b + GRIDX;
        if (bn < NB) {
            const float4* xs = (const float4*)(x + (size_t)bn * (NHEX * HD));
            float4 a0 = xs[2 * g0], a1 = xs[2 * g0 + 1];
            float4 c0, c1;
            if (v1) { c0 = xs[2 * g1]; c1 = xs[2 * g1 + 1]; }
            *(uint4*)(nxt + dst0) = make_uint4(pk(a0.x, a0.y), pk(a0.z, a0.w),
                                               pk(a1.x, a1.y), pk(a1.z, a1.w));
            if (v1)
                *(uint4*)(nxt + dst1) = make_uint4(pk(c0.x, c0.y), pk(c0.z, c0.w),
                                                   pk(c1.x, c1.y), pk(c1.z, c1.w));
        }

        float acc[2][2][4];
#pragma unroll
        for (int u = 0; u < 2; u++)
#pragma unroll
            for (int nf = 0; nf < 2; nf++)
#pragma unroll
                for (int i = 0; i < 4; i++) acc[u][nf][i] = 0.f;

        const char* Wp0 = Wc + (wn * 16 + lr) * WROWB + 16 * lc;

#pragma unroll 1
        for (int c = 0; c < NCHUNK; c++) {
            const int off  = OFFC[c];
            const bool adj = (c < 2 || c > 4);

            const char* wp = Wp0 + c * 128;
            uint4 w00 = *(const uint4*)(wp);
            uint4 w01 = *(const uint4*)(wp + 64);
            uint4 w10 = *(const uint4*)(wp + 8 * WROWB);
            uint4 w11 = *(const uint4*)(wp + 8 * WROWB + 64);

#pragma unroll
            for (int u = 0; u < 2; u++) {
                if (u == 0 || wm < 5) {          // frag f = 2wm+u valid (f < 11)
                    const int p0 = base2[u][0] + off - (adj ? parC[u][0] : 0);
                    const int p1 = base2[u][1] + off - (adj ? parC[u][1] : 0);
                    uint4 a00 = *(const uint4*)(cur + p0);
                    uint4 a01 = *(const uint4*)(cur + p0 + 64);
                    uint4 a10 = *(const uint4*)(cur + p1);
                    uint4 a11 = *(const uint4*)(cur + p1 + 64);
                    mma16816(acc[u][0], a00.x, a10.x, a00.y, a10.y, w00.x, w00.y);
                    mma16816(acc[u][1], a00.x, a10.x, a00.y, a10.y, w10.x, w10.y);
                    mma16816(acc[u][0], a00.z, a10.z, a00.w, a10.w, w00.z, w00.w);
                    mma16816(acc[u][1], a00.z, a10.z, a00.w, a10.w, w10.z, w10.w);
                    mma16816(acc[u][0], a01.x, a11.x, a01.y, a11.y, w01.x, w01.y);
                    mma16816(acc[u][1], a01.x, a11.x, a01.y, a11.y, w11.x, w11.y);
                    mma16816(acc[u][0], a01.z, a11.z, a01.w, a11.w, w01.z, w01.w);
                    mma16816(acc[u][1], a01.z, a11.z, a01.w, a11.w, w11.z, w11.w);
                }
            }
        }

        // ---- epilogue: bias + masked stores ----
        float* ob = out + (size_t)b * (NHEX * OUTD);
#pragma unroll
        for (int u = 0; u < 2; u++) {
            if (u == 0 || wm < 5) {
                const int f = 2 * wm + u;
                const int n1 = f * 16 + lr, n2 = n1 + 8;
#pragma unroll
                for (int nf = 0; nf < 2; nf++) {
                    const int cc = wn * 16 + nf * 8 + 2 * lc;
                    if (n1 < NHEX) {
                        float2 v = make_float2(acc[u][nf][0] + bv[nf].x,
                                               acc[u][nf][1] + bv[nf].y);
                        *(float2*)(ob + n1 * OUTD + cc) = v;
                    }
                    if (n2 < NHEX) {
                        float2 v = make_float2(acc[u][nf][2] + bv[nf].x,
                                               acc[u][nf][3] + bv[nf].y);
                        *(float2*)(ob + n2 * OUTD + cc) = v;
                    }
                }
            }
        }

        __syncthreads();   // publish next buffer; retire current buffer
        ib ^= 1;
    }
}

extern "C" void kernel_launch(void* const* d_in, const int* in_sizes, int n_in,
                              void* d_out, int out_size)
{
    const float* x    = (const float*)d_in[0];
    const float* W    = (const float*)d_in[1];
    const float* bias = (const float*)d_in[2];
    float* out = (float*)d_out;

    cudaFuncSetAttribute(hexconv_mma,
                         cudaFuncAttributeMaxDynamicSharedMemorySize,
                         (int)SMEM_BYTES);
    hexconv_mma<<<GRIDX, THREADS, SMEM_BYTES>>>(x, W, bias, out);
}

// round 12
// speedup vs baseline: 1.0577x; 1.0577x over previous
#include <cuda_runtime.h>
#include <cuda_fp16.h>
#include <cstdint>

// HexConv, persistent-CTA fp16 mma.sync (m16n8k16, f32 accum), split-warp design:
//   512 threads = 2 independent groups of 8 warps. Each group = 4 M-groups x 2
//   N-halves (32 cols), processes its OWN batch stream (b = bid + 152*(2k+g)) with
//   its OWN double-buffered fp16 padded grid; W (fp16, SMEM) is shared read-only.
//   Groups sync only via named barriers (bar.sync 1+g, 256) -> fully decoupled.
// Traffic: A = 616 + W = 448 LDS.128 per batch (0.63x of round-10 layout).
// K-permutation: per 32-k superblock, thread lc owns orig d = 8lc..8lc+7.

#define NHEX   165
#define HD     64
#define OUTD   64
#define NCHUNK 7
#define CELLB  192
#define WROWB  960
#define NB     2048
#define THREADS 512
#define GRIDX  152
#define GSTEP  (2 * GRIDX)          // 304

#define G_BYTES (221 * CELLB)                  // 42432 per buffer
#define W_BYTES (OUTD * WROWB)                 // 61440
#define SMEM_BYTES (4 * G_BYTES + W_BYTES)     // 231168 (<= 232448 block max)

__constant__ int OFFC[7] = {-17 * CELLB, -16 * CELLB, -1 * CELLB, 0,
                            1 * CELLB, 17 * CELLB, 18 * CELLB};

static __device__ __forceinline__ uint32_t pk(float a, float b) {
    __half2 h = __floats2half2_rn(a, b);
    return *(uint32_t*)&h;
}
static __device__ __forceinline__ void gbar(int grp) {
    asm volatile("bar.sync %0, 256;" :: "r"(1 + grp) : "memory");
}
static __device__ __forceinline__ void mma16816(float* c,
                                                uint32_t a0, uint32_t a1, uint32_t a2, uint32_t a3,
                                                uint32_t b0, uint32_t b1) {
    asm volatile(
        "mma.sync.aligned.m16n8k16.row.col.f32.f16.f16.f32 "
        "{%0,%1,%2,%3}, {%4,%5,%6,%7}, {%8,%9}, {%0,%1,%2,%3};"
        : "+f"(c[0]), "+f"(c[1]), "+f"(c[2]), "+f"(c[3])
        : "r"(a0), "r"(a1), "r"(a2), "r"(a3), "r"(b0), "r"(b1));
}

__global__ void __launch_bounds__(THREADS, 1)
hexconv_mma(const float* __restrict__ x, const float* __restrict__ W,
            const float* __restrict__ bias, float* __restrict__ out)
{
    extern __shared__ char smem[];
    char* Wc = smem + 4 * G_BYTES;       // shared W, fp16
    const int tid  = threadIdx.x;
    const int grp  = tid >> 8;           // 0 or 1
    const int gtid = tid & 255;          // thread within group
    char* GB[2] = { smem + (2 * grp) * G_BYTES,
                    smem + (2 * grp + 1) * G_BYTES };

    // ---- one-time: zero all 4 grid buffers ----
    for (int i = tid; i < 4 * G_BYTES / 16; i += THREADS)
        ((uint4*)smem)[i] = make_uint4(0, 0, 0, 0);

    // ---- one-time: stage W as fp16 ----
    const float4* Wg4 = (const float4*)W;
    for (int i = tid; i < OUTD * 112; i += THREADS) {
        int o = i / 112, k4 = i - o * 112;
        float4 v = Wg4[i];
        *(uint2*)(Wc + o * WROWB + k4 * 8) = make_uint2(pk(v.x, v.y), pk(v.z, v.w));
    }

    // ---- staging map: 1320 uint4 groups per batch; <=6 per thread ----
    int gdst[6];
#pragma unroll
    for (int j = 0; j < 6; j++) {
        int g = gtid + 256 * j;
        if (g < NHEX * 8) {
            int n = g >> 3, d8 = g & 7;
            int hr = n / 15, hc = n - 15 * hr;
            gdst[j] = ((hr + 1) * 17 + (hc + 1)) * CELLB + d8 * 16;
        } else gdst[j] = -1;
    }

    // ---- warp geometry within group: 8 warps = 4 M-groups x 2 N-halves ----
    const int wg = (tid >> 5) & 7, lane = tid & 31;
    const int wm = wg & 3;         // M group: frags f = wm + 4u
    const int wn = wg >> 2;        // N half (32 cols)
    const int lr = lane >> 2, lc = lane & 3;

    float2 bv[4];
#pragma unroll
    for (int nf = 0; nf < 4; nf++)
        bv[nf] = ((const float2*)bias)[(wn * 32 + nf * 8 + 2 * lc) >> 1];

    // fragment row bases (clamped): rows n = 16f + h*8 + lr
    int base2[3][2], parC[3][2];
#pragma unroll
    for (int u = 0; u < 3; u++) {
        const int f = wm + 4 * u;
#pragma unroll
        for (int h = 0; h < 2; h++) {
            int n = f * 16 + h * 8 + lr;
            if (n > 164) n = 164;
            int hr = n / 15, hc = n - 15 * hr;
            base2[u][h] = ((hr + 1) * 17 + (hc + 1)) * CELLB + 16 * lc;
            parC[u][h]  = ((hr + 1) & 1) ? CELLB : 0;
        }
    }

    __syncthreads();   // zero + W staging complete; groups decouple from here

    const int b0 = blockIdx.x + GRIDX * grp;

    // ---- convert first batch into group's buffer 0 ----
    if (b0 < NB) {
        const float4* xs = (const float4*)(x + (size_t)b0 * (NHEX * HD));
#pragma unroll
        for (int j = 0; j < 6; j++)
            if (gdst[j] >= 0) {
                int g = gtid + 256 * j;
                float4 v0 = xs[2 * g], v1 = xs[2 * g + 1];
                *(uint4*)(GB[0] + gdst[j]) =
                    make_uint4(pk(v0.x, v0.y), pk(v0.z, v0.w),
                               pk(v1.x, v1.y), pk(v1.z, v1.w));
            }
    }
    gbar(grp);

    int ib = 0;
    for (int b = b0; b < NB; b += GSTEP) {
        char* cur = GB[ib];
        char* nxt = GB[ib ^ 1];

        // ---- convert next batch into idle buffer (overlaps compute, no barrier) ----
        const int bn = b + GSTEP;
        if (bn < NB) {
            const float4* xs = (const float4*)(x + (size_t)bn * (NHEX * HD));
#pragma unroll
            for (int j = 0; j < 6; j++)
                if (gdst[j] >= 0) {
                    int g = gtid + 256 * j;
                    float4 v0 = xs[2 * g], v1 = xs[2 * g + 1];
                    *(uint4*)(nxt + gdst[j]) =
                        make_uint4(pk(v0.x, v0.y), pk(v0.z, v0.w),
                                   pk(v1.x, v1.y), pk(v1.z, v1.w));
                }
        }

        float acc[3][4][4];
#pragma unroll
        for (int u = 0; u < 3; u++)
#pragma unroll
            for (int nf = 0; nf < 4; nf++)
#pragma unroll
                for (int i = 0; i < 4; i++) acc[u][nf][i] = 0.f;

        const char* Wp0 = Wc + (wn * 32 + lr) * WROWB + 16 * lc;

#pragma unroll 1
        for (int c = 0; c < NCHUNK; c++) {
            const int off  = OFFC[c];
            const bool adj = (c < 2 || c > 4);
            int p0[3], p1[3];
#pragma unroll
            for (int u = 0; u < 3; u++) {
                p0[u] = base2[u][0] + off - (adj ? parC[u][0] : 0);
                p1[u] = base2[u][1] + off - (adj ? parC[u][1] : 0);
            }
            const char* wp = Wp0 + c * 128;
#pragma unroll
            for (int sub = 0; sub < 2; sub++) {
                uint4 w[4];
#pragma unroll
                for (int nf = 0; nf < 4; nf++)
                    w[nf] = *(const uint4*)(wp + nf * (8 * WROWB) + sub * 64);
#pragma unroll
                for (int u = 0; u < 3; u++) {
                    if (u < 2 || wm < 3) {     // frag f = wm+4u valid (f < 11)
                        uint4 a0 = *(const uint4*)(cur + p0[u] + sub * 64);
                        uint4 a1 = *(const uint4*)(cur + p1[u] + sub * 64);
#pragma unroll
                        for (int nf = 0; nf < 4; nf++) {
                            mma16816(acc[u][nf], a0.x, a1.x, a0.y, a1.y, w[nf].x, w[nf].y);
                            mma16816(acc[u][nf], a0.z, a1.z, a0.w, a1.w, w[nf].z, w[nf].w);
                        }
                    }
                }
            }
        }

        // ---- epilogue: bias + masked stores ----
        float* ob = out + (size_t)b * (NHEX * OUTD);
#pragma unroll
        for (int u = 0; u < 3; u++) {
            if (u < 2 || wm < 3) {
                const int f = wm + 4 * u;
                const int n1 = f * 16 + lr, n2 = n1 + 8;
#pragma unroll
                for (int nf = 0; nf < 4; nf++) {
                    const int cc = wn * 32 + nf * 8 + 2 * lc;
                    if (n1 < NHEX) {
                        float2 v = make_float2(acc[u][nf][0] + bv[nf].x,
                                               acc[u][nf][1] + bv[nf].y);
                        *(float2*)(ob + n1 * OUTD + cc) = v;
                    }
                    if (n2 < NHEX) {
                        float2 v = make_float2(acc[u][nf][2] + bv[nf].x,
                                               acc[u][nf][3] + bv[nf].y);
                        *(float2*)(ob + n2 * OUTD + cc) = v;
                    }
                }
            }
        }

        gbar(grp);   // publish next buffer; retire current (group-local)
        ib ^= 1;
    }
}

extern "C" void kernel_launch(void* const* d_in, const int* in_sizes, int n_in,
                              void* d_out, int out_size)
{
    const float* x    = (const float*)d_in[0];
    const float* W    = (const float*)d_in[1];
    const float* bias = (const float*)d_in[2];
    float* out = (float*)d_out;

    cudaFuncSetAttribute(hexconv_mma,
                         cudaFuncAttributeMaxDynamicSharedMemorySize,
                         (int)SMEM_BYTES);
    hexconv_mma<<<GRIDX, THREADS, SMEM_BYTES>>>(x, W, bias, out);
}

// round 13
// speedup vs baseline: 1.1079x; 1.0475x over previous
#include <cuda_runtime.h>
#include <cuda_fp16.h>
#include <cstdint>

// HexConv, persistent fp16 mma.sync (m16n8k16, f32 accum), 2 CTAs/SM:
//   256 threads/CTA = 8 warps = 4 M-groups x 2 N-halves (32 cols). Each CTA owns
//   its own batch stream (b = bid + 304k), its own fp16 padded grid + W in SMEM.
//   Sibling CTA on the same SM hides barrier/LDG stalls.
//   Register diet vs rounds 9/12: no prefetch arrays, recomputed staging addrs,
//   base/baseAdj precompute. Demand ~115 regs < 128 cap at 2 CTAs/SM.
// K-permutation: per 32-k superblock, thread lc owns orig d = 8lc..8lc+7 -> all
// operand traffic is LDS.128; CELLB/WROWB == 64 mod 128 -> conflict-free phases.

#define NHEX   165
#define HD     64
#define OUTD   64
#define NCHUNK 7
#define CELLB  192
#define WROWB  960
#define NB     2048
#define THREADS 256
#define GRIDX  304

#define G_BYTES (221 * CELLB)              // 42432
#define W_BYTES (OUTD * WROWB)             // 61440
#define SMEM_BYTES (G_BYTES + W_BYTES)     // 103872  (x2 CTAs = 207744 <= SM cap)

__constant__ int OFFC[7] = {-17 * CELLB, -16 * CELLB, -1 * CELLB, 0,
                            1 * CELLB, 17 * CELLB, 18 * CELLB};

static __device__ __forceinline__ uint32_t pk(float a, float b) {
    __half2 h = __floats2half2_rn(a, b);
    return *(uint32_t*)&h;
}
static __device__ __forceinline__ void mma16816(float* c,
                                                uint32_t a0, uint32_t a1, uint32_t a2, uint32_t a3,
                                                uint32_t b0, uint32_t b1) {
    asm volatile(
        "mma.sync.aligned.m16n8k16.row.col.f32.f16.f16.f32 "
        "{%0,%1,%2,%3}, {%4,%5,%6,%7}, {%8,%9}, {%0,%1,%2,%3};"
        : "+f"(c[0]), "+f"(c[1]), "+f"(c[2]), "+f"(c[3])
        : "r"(a0), "r"(a1), "r"(a2), "r"(a3), "r"(b0), "r"(b1));
}

__global__ void __launch_bounds__(THREADS, 2)
hexconv_mma(const float* __restrict__ x, const float* __restrict__ W,
            const float* __restrict__ bias, float* __restrict__ out)
{
    extern __shared__ char smem[];
    char* Gc = smem;                     // padded grid, fp16
    char* Wc = smem + G_BYTES;           // W, fp16
    const int tid = threadIdx.x;

    // ---- one-time: zero padded grid (pad cells stay zero forever) ----
    for (int i = tid; i < G_BYTES / 16; i += THREADS)
        ((uint4*)Gc)[i] = make_uint4(0, 0, 0, 0);

    // ---- one-time: stage W as fp16 ----
    const float4* Wg4 = (const float4*)W;
    for (int i = tid; i < OUTD * 112; i += THREADS) {
        int o = i / 112, k4 = i - o * 112;
        float4 v = Wg4[i];
        *(uint2*)(Wc + o * WROWB + k4 * 8) = make_uint2(pk(v.x, v.y), pk(v.z, v.w));
    }

    // ---- warp geometry: 8 warps = 4 M-groups x 2 N-halves ----
    const int wid = tid >> 5, lane = tid & 31;
    const int wm = wid & 3;        // M group: frags f = wm + 4u
    const int wn = wid >> 2;       // N half (32 cols)
    const int lr = lane >> 2, lc = lane & 3;

    float2 bv[4];
#pragma unroll
    for (int nf = 0; nf < 4; nf++)
        bv[nf] = ((const float2*)bias)[(wn * 32 + nf * 8 + 2 * lc) >> 1];

    // fragment row bases (clamped): rows n = 16f + h*8 + lr.
    // base   : for non-adjusted chunks (c = 2,3,4)
    // baseAdj: for adjusted chunks    (c = 0,1,5,6)  (= base - CELLB if row odd)
    int base[3][2], baseAdj[3][2];
#pragma unroll
    for (int u = 0; u < 3; u++) {
        const int f = wm + 4 * u;
#pragma unroll
        for (int h = 0; h < 2; h++) {
            int n = f * 16 + h * 8 + lr;
            if (n > 164) n = 164;
            int hr = n / 15, hc = n - 15 * hr;
            int bb = ((hr + 1) * 17 + (hc + 1)) * CELLB + 16 * lc;
            base[u][h]    = bb;
            baseAdj[u][h] = bb - (((hr + 1) & 1) ? CELLB : 0);
        }
    }

    __syncthreads();   // zero + W staging complete

    for (int b = blockIdx.x; b < NB; b += GRIDX) {
        // ---- convert batch b -> fp16 grid (addresses recomputed, no reg arrays) ----
        {
            const float4* xs = (const float4*)(x + (size_t)b * (NHEX * HD));
#pragma unroll
            for (int j = 0; j < 6; j++) {
                int g = tid + THREADS * j;           // group of 8 floats
                if (g < NHEX * 8) {
                    int n = g >> 3, d8 = g & 7;
                    int hr = n / 15, hc = n - 15 * hr;
                    int dst = ((hr + 1) * 17 + (hc + 1)) * CELLB + d8 * 16;
                    float4 v0 = xs[2 * g], v1 = xs[2 * g + 1];
                    *(uint4*)(Gc + dst) = make_uint4(pk(v0.x, v0.y), pk(v0.z, v0.w),
                                                     pk(v1.x, v1.y), pk(v1.z, v1.w));
                }
            }
        }
        __syncthreads();   // grid ready

        float acc[3][4][4];
#pragma unroll
        for (int u = 0; u < 3; u++)
#pragma unroll
            for (int nf = 0; nf < 4; nf++)
#pragma unroll
                for (int i = 0; i < 4; i++) acc[u][nf][i] = 0.f;

        const char* Wp0 = Wc + (wn * 32 + lr) * WROWB + 16 * lc;

#pragma unroll 1
        for (int c = 0; c < NCHUNK; c++) {
            const int off  = OFFC[c];
            const bool adj = (c < 2 || c > 4);
            const char* wp = Wp0 + c * 128;
#pragma unroll
            for (int sub = 0; sub < 2; sub++) {
                uint4 w[4];
#pragma unroll
                for (int nf = 0; nf < 4; nf++)
                    w[nf] = *(const uint4*)(wp + nf * (8 * WROWB) + sub * 64);
#pragma unroll
                for (int u = 0; u < 3; u++) {
                    if (u < 2 || wm < 3) {     // frag f = wm+4u valid (f < 11)
                        const int p0 = (adj ? baseAdj[u][0] : base[u][0]) + off + sub * 64;
                        const int p1 = (adj ? baseAdj[u][1] : base[u][1]) + off + sub * 64;
                        uint4 a0 = *(const uint4*)(Gc + p0);
                        uint4 a1 = *(const uint4*)(Gc + p1);
#pragma unroll
                        for (int nf = 0; nf < 4; nf++) {
                            mma16816(acc[u][nf], a0.x, a1.x, a0.y, a1.y, w[nf].x, w[nf].y);
                            mma16816(acc[u][nf], a0.z, a1.z, a0.w, a1.w, w[nf].z, w[nf].w);
                        }
                    }
                }
            }
        }

        // ---- epilogue: bias + masked stores ----
        float* ob = out + (size_t)b * (NHEX * OUTD);
#pragma unroll
        for (int u = 0; u < 3; u++) {
            if (u < 2 || wm < 3) {
                const int f = wm + 4 * u;
                const int n1 = f * 16 + lr, n2 = n1 + 8;
#pragma unroll
                for (int nf = 0; nf < 4; nf++) {
                    const int cc = wn * 32 + nf * 8 + 2 * lc;
                    if (n1 < NHEX) {
                        float2 v = make_float2(acc[u][nf][0] + bv[nf].x,
                                               acc[u][nf][1] + bv[nf].y);
                        *(float2*)(ob + n1 * OUTD + cc) = v;
                    }
                    if (n2 < NHEX) {
                        float2 v = make_float2(acc[u][nf][2] + bv[nf].x,
                                               acc[u][nf][3] + bv[nf].y);
                        *(float2*)(ob + n2 * OUTD + cc) = v;
                    }
                }
            }
        }
        __syncthreads();   // retire grid before next batch's convert
    }
}

extern "C" void kernel_launch(void* const* d_in, const int* in_sizes, int n_in,
                              void* d_out, int out_size)
{
    const float* x    = (const float*)d_in[0];
    const float* W    = (const float*)d_in[1];
    const float* bias = (const float*)d_in[2];
    float* out = (float*)d_out;

    cudaFuncSetAttribute(hexconv_mma,
                         cudaFuncAttributeMaxDynamicSharedMemorySize,
                         (int)SMEM_BYTES);
    hexconv_mma<<<GRIDX, THREADS, SMEM_BYTES>>>(x, W, bias, out);
}